// round 13
// baseline (speedup 1.0000x reference)
#include <cuda_runtime.h>
#include <math_constants.h>
#include <math.h>

#define NTOK_PER_BLOCK 128
#define NEXPERT 64
#define TOPK 8

// Exact CUDA transcription of Eigen's pexp_float (Cephes expf), FMA path —
// what XLA:CPU's vectorized exp executes on aarch64 NEON. All ops are IEEE
// fp32 (fmaf/floorf/mul), so this is bitwise-identical to the NEON result.
__device__ __forceinline__ float eigen_pexp(float _x) {
    const float cst_1         = 1.0f;
    const float cst_half      = 0.5f;
    const float cst_exp_hi    = 88.723f;
    const float cst_exp_lo    = -88.723f;
    const float cst_LOG2EF    = 1.44269504088896341f;
    const float cst_nln2      = -0.6931471805599453f;   // FMA path constant
    const float cst_p0        = 1.9875691500E-4f;
    const float cst_p1        = 1.3981999507E-3f;
    const float cst_p2        = 8.3334519073E-3f;
    const float cst_p3        = 4.1665795894E-2f;
    const float cst_p4        = 1.6666665459E-1f;
    const float cst_p5        = 5.0000001201E-1f;

    float x = fmaxf(fminf(_x, cst_exp_hi), cst_exp_lo);
    float m = floorf(fmaf(x, cst_LOG2EF, cst_half));
    float r = fmaf(m, cst_nln2, x);          // EIGEN_VECTORIZE_FMA branch
    float r2 = r * r;
    float r3 = r2 * r;

    float y  = fmaf(cst_p0, r, cst_p1);      // Eigen's ILP-ordered polynomial
    float y1 = fmaf(cst_p3, r, cst_p4);
    float y2 = r + cst_1;
    y  = fmaf(y,  r,  cst_p2);
    y1 = fmaf(y1, r,  cst_p5);
    y  = fmaf(y,  r3, y1);
    y  = fmaf(y,  r2, y2);

    // pldexp(y, m): multiply by 2^m — exact (power of two), any realization
    // is bitwise-identical. m in [-127, 127] for clamped x; here m in [-128,129)
    // can't occur post-clamp with our inputs (softmax args <= 0).
    float two_m = __int_as_float((127 + (int)m) << 23);
    float res = y * two_m;
    return fmaxf(res, _x);                   // Eigen's final pmax(res, _x)
}

// Static shared: W transposed (16KB) + spilled scores (32KB) = 48KB exactly.
__global__ __launch_bounds__(128) void moe_gate_kernel(
    const float* __restrict__ x,      // [n_tokens, 64]
    const float* __restrict__ W,      // [64, 64]
    float* __restrict__ out,          // [n_tokens*8 weights][n_tokens*8 indices-as-float]
    int n_tokens)
{
    __shared__ float Wt[64 * 64];       // Wt[k*64 + f] = W[f*64 + k]
    __shared__ float tS[64 * 128];      // tS[k*128 + tid] — per-thread column, conflict-free

    const int tid = threadIdx.x;

    for (int i = tid; i < 64 * 64; i += 128) {
        int f = i >> 6;
        int k = i & 63;
        Wt[k * 64 + f] = W[i];
    }
    __syncthreads();

    long long token = (long long)blockIdx.x * NTOK_PER_BLOCK + tid;
    if (token >= n_tokens) return;   // no barriers after this point

    // ---- fp32 GEMM, serial in-order FMA over k (matches Eigen gebp / the
    //      reference: R12 proved serial-k is the reference's order) ----
    const float4* __restrict__ xrow = (const float4*)(x + token * 64);

    float acc[64];
    #pragma unroll
    for (int f = 0; f < 64; f++) acc[f] = 0.0f;

    #pragma unroll 2
    for (int kk = 0; kk < 16; kk++) {
        float4 xv = __ldg(xrow + kk);
        #pragma unroll
        for (int q = 0; q < 4; q++) {
            float xq = (q == 0) ? xv.x : (q == 1) ? xv.y : (q == 2) ? xv.z : xv.w;
            const float4* __restrict__ w4 = (const float4*)(Wt + (kk * 4 + q) * 64);
            #pragma unroll
            for (int e4 = 0; e4 < 16; e4++) {
                float4 w = w4[e4];   // broadcast LDS.128 (same addr all lanes)
                acc[e4 * 4 + 0] = fmaf(xq, w.x, acc[e4 * 4 + 0]);
                acc[e4 * 4 + 1] = fmaf(xq, w.y, acc[e4 * 4 + 1]);
                acc[e4 * 4 + 2] = fmaf(xq, w.z, acc[e4 * 4 + 2]);
                acc[e4 * 4 + 3] = fmaf(xq, w.w, acc[e4 * 4 + 3]);
            }
        }
    }

    // ---- softmax: Eigen pexp(l - max), pairwise tree sum, IEEE division ----
    float m0 = acc[0];
    #pragma unroll
    for (int k = 1; k < 64; k++) m0 = fmaxf(m0, acc[k]);   // max is order-exact

    #pragma unroll
    for (int k = 0; k < 64; k++) acc[k] = eigen_pexp(acc[k] - m0);

    float red[32];
    #pragma unroll
    for (int k = 0; k < 32; k++) red[k] = acc[k] + acc[k + 32];
    #pragma unroll
    for (int s = 16; s >= 1; s >>= 1) {
        #pragma unroll
        for (int k = 0; k < 16; k++)
            if (k < s) red[k] = red[k] + red[k + s];
    }
    float S = red[0];

    // t = e / S (IEEE): division is monotonic in e, so my ordering over t
    // equals the reference's ordering over its t whenever e matches bitwise.
    #pragma unroll
    for (int k = 0; k < 64; k++) acc[k] = __fdiv_rn(acc[k], S);

    // ---- group maxes over scores (2-level tournament, level 1) ----
    float g[8];
    #pragma unroll
    for (int j = 0; j < 8; j++) {
        float m = acc[j * 8];
        #pragma unroll
        for (int q = 1; q < 8; q++) m = fmaxf(m, acc[j * 8 + q]);
        g[j] = m;
    }

    // Spill scores: addr = k*128 + tid -> conflict-free for any dynamic k.
    #pragma unroll
    for (int k = 0; k < 64; k++) tS[k * 128 + tid] = acc[k];

    // ---- 8 extraction passes over fp32 scores ----
    // Smallest-group-then-smallest-slot equality scan == smallest-index
    // tie-break on bitwise-equal scores — jax.lax.top_k's stable order.
    float oval[TOPK];
    int   oidx[TOPK];

    #pragma unroll
    for (int p = 0; p < TOPK; p++) {
        float m = g[0];
        #pragma unroll
        for (int j = 1; j < 8; j++) m = fmaxf(m, g[j]);

        int jstar = 7;
        #pragma unroll
        for (int j = 6; j >= 0; j--) jstar = (g[j] == m) ? j : jstar;

        int base = jstar * 8;
        float vq[8];
        #pragma unroll
        for (int q = 0; q < 8; q++) vq[q] = tS[(base + q) * 128 + tid];

        int qstar = 7;
        #pragma unroll
        for (int q = 6; q >= 0; q--) qstar = (vq[q] == m) ? q : qstar;

        tS[(base + qstar) * 128 + tid] = -CUDART_INF_F;
        float ng = -CUDART_INF_F;
        #pragma unroll
        for (int q = 0; q < 8; q++) ng = fmaxf(ng, (q == qstar) ? -CUDART_INF_F : vq[q]);
        #pragma unroll
        for (int j = 0; j < 8; j++) g[j] = (j == jstar) ? ng : g[j];

        oval[p] = m;              // softmax weight (fp32 score)
        oidx[p] = base + qstar;
    }

    // ---- write outputs: weights then indices (as float32) ----
    float* outW = out + token * 8;
    float* outI = out + (long long)n_tokens * 8 + token * 8;

    float4 w0 = make_float4(oval[0], oval[1], oval[2], oval[3]);
    float4 w1 = make_float4(oval[4], oval[5], oval[6], oval[7]);
    *reinterpret_cast<float4*>(outW + 0) = w0;
    *reinterpret_cast<float4*>(outW + 4) = w1;

    float4 i0 = make_float4((float)oidx[0], (float)oidx[1], (float)oidx[2], (float)oidx[3]);
    float4 i1 = make_float4((float)oidx[4], (float)oidx[5], (float)oidx[6], (float)oidx[7]);
    *reinterpret_cast<float4*>(outI + 0) = i0;
    *reinterpret_cast<float4*>(outI + 4) = i1;
}

extern "C" void kernel_launch(void* const* d_in, const int* in_sizes, int n_in,
                              void* d_out, int out_size)
{
    const float* x = (const float*)d_in[0];   // hidden_states [n_tokens, 64]
    const float* W = (const float*)d_in[1];   // weight        [64, 64]
    float* out = (float*)d_out;

    int n_tokens = in_sizes[0] / NEXPERT;
    int blocks = (n_tokens + NTOK_PER_BLOCK - 1) / NTOK_PER_BLOCK;

    moe_gate_kernel<<<blocks, NTOK_PER_BLOCK>>>(x, W, out, n_tokens);
}

// round 14
// speedup vs baseline: 1.0163x; 1.0163x over previous
#include <cuda_runtime.h>
#include <math_constants.h>
#include <math.h>

#define NTHREADS 64
#define TOKENS_PER_BLOCK 128
#define NEXPERT 64
#define TOPK 8

// Exact CUDA transcription of Eigen's pexp_float (Cephes expf), FMA path —
// what XLA:CPU's vectorized exp executes on aarch64 NEON. All ops are IEEE
// fp32 (fmaf/floorf/mul), so this is bitwise-identical to the NEON result.
__device__ __forceinline__ float eigen_pexp(float _x) {
    const float cst_1         = 1.0f;
    const float cst_half      = 0.5f;
    const float cst_exp_hi    = 88.723f;
    const float cst_exp_lo    = -88.723f;
    const float cst_LOG2EF    = 1.44269504088896341f;
    const float cst_nln2      = -0.6931471805599453f;
    const float cst_p0        = 1.9875691500E-4f;
    const float cst_p1        = 1.3981999507E-3f;
    const float cst_p2        = 8.3334519073E-3f;
    const float cst_p3        = 4.1665795894E-2f;
    const float cst_p4        = 1.6666665459E-1f;
    const float cst_p5        = 5.0000001201E-1f;

    float x = fmaxf(fminf(_x, cst_exp_hi), cst_exp_lo);
    float m = floorf(fmaf(x, cst_LOG2EF, cst_half));
    float r = fmaf(m, cst_nln2, x);
    float r2 = r * r;
    float r3 = r2 * r;

    float y  = fmaf(cst_p0, r, cst_p1);
    float y1 = fmaf(cst_p3, r, cst_p4);
    float y2 = r + cst_1;
    y  = fmaf(y,  r,  cst_p2);
    y1 = fmaf(y1, r,  cst_p5);
    y  = fmaf(y,  r3, y1);
    y  = fmaf(y,  r2, y2);

    float two_m = __int_as_float((127 + (int)m) << 23);
    float res = y * two_m;
    return fmaxf(res, _x);
}

// Per-token epilogue: bitwise-identical to the R13 pipeline.
// tScol points at tS + lt (column stride 128 floats, conflict-free banks).
__device__ __forceinline__ void epilogue(float (&acc)[64], float* tScol,
                                         float* outW, float* outI)
{
    float m0 = acc[0];
    #pragma unroll
    for (int k = 1; k < 64; k++) m0 = fmaxf(m0, acc[k]);

    #pragma unroll
    for (int k = 0; k < 64; k++) acc[k] = eigen_pexp(acc[k] - m0);

    float red[32];
    #pragma unroll
    for (int k = 0; k < 32; k++) red[k] = acc[k] + acc[k + 32];
    #pragma unroll
    for (int s = 16; s >= 1; s >>= 1) {
        #pragma unroll
        for (int k = 0; k < 16; k++)
            if (k < s) red[k] = red[k] + red[k + s];
    }
    float S = red[0];

    #pragma unroll
    for (int k = 0; k < 64; k++) acc[k] = __fdiv_rn(acc[k], S);

    float g[8];
    #pragma unroll
    for (int j = 0; j < 8; j++) {
        float m = acc[j * 8];
        #pragma unroll
        for (int q = 1; q < 8; q++) m = fmaxf(m, acc[j * 8 + q]);
        g[j] = m;
    }

    #pragma unroll
    for (int k = 0; k < 64; k++) tScol[k * 128] = acc[k];

    float oval[TOPK];
    int   oidx[TOPK];

    #pragma unroll
    for (int p = 0; p < TOPK; p++) {
        float m = g[0];
        #pragma unroll
        for (int j = 1; j < 8; j++) m = fmaxf(m, g[j]);

        int jstar = 7;
        #pragma unroll
        for (int j = 6; j >= 0; j--) jstar = (g[j] == m) ? j : jstar;

        int base = jstar * 8;
        float vq[8];
        #pragma unroll
        for (int q = 0; q < 8; q++) vq[q] = tScol[(base + q) * 128];

        int qstar = 7;
        #pragma unroll
        for (int q = 6; q >= 0; q--) qstar = (vq[q] == m) ? q : qstar;

        tScol[(base + qstar) * 128] = -CUDART_INF_F;
        float ng = -CUDART_INF_F;
        #pragma unroll
        for (int q = 0; q < 8; q++) ng = fmaxf(ng, (q == qstar) ? -CUDART_INF_F : vq[q]);
        #pragma unroll
        for (int j = 0; j < 8; j++) g[j] = (j == jstar) ? ng : g[j];

        oval[p] = m;
        oidx[p] = base + qstar;
    }

    float4 w0 = make_float4(oval[0], oval[1], oval[2], oval[3]);
    float4 w1 = make_float4(oval[4], oval[5], oval[6], oval[7]);
    *reinterpret_cast<float4*>(outW + 0) = w0;
    *reinterpret_cast<float4*>(outW + 4) = w1;

    float4 i0 = make_float4((float)oidx[0], (float)oidx[1], (float)oidx[2], (float)oidx[3]);
    float4 i1 = make_float4((float)oidx[4], (float)oidx[5], (float)oidx[6], (float)oidx[7]);
    *reinterpret_cast<float4*>(outI + 0) = i0;
    *reinterpret_cast<float4*>(outI + 4) = i1;
}

// Static shared: Wt (16KB) + tS for 128 tokens (32KB) = 48KB.
// 64 threads x 2 tokens/thread: each broadcast LDS.128 of W feeds 8 FMAs.
__global__ __launch_bounds__(NTHREADS) void moe_gate_kernel(
    const float* __restrict__ x,      // [n_tokens, 64]
    const float* __restrict__ W,      // [64, 64]
    float* __restrict__ out,          // [n_tokens*8 weights][n_tokens*8 indices-as-float]
    int n_tokens)
{
    __shared__ float Wt[64 * 64];       // Wt[k*64 + f] = W[f*64 + k]
    __shared__ float tS[64 * 128];      // tS[k*128 + lt], lt in [0,128)

    const int tid = threadIdx.x;

    for (int i = tid; i < 64 * 64; i += NTHREADS) {
        int f = i >> 6;
        int k = i & 63;
        Wt[k * 64 + f] = W[i];
    }
    __syncthreads();

    long long base   = (long long)blockIdx.x * TOKENS_PER_BLOCK;
    long long token0 = base + tid;          // lt = tid
    long long token1 = base + tid + 64;     // lt = tid + 64
    if (token0 >= n_tokens) return;         // no barriers after this point
    bool has1 = (token1 < n_tokens);

    // ---- fp32 GEMM for 2 tokens, serial in-order FMA over k per expert
    //      (bitwise-identical chain per token to the R13 passing kernel) ----
    const float4* __restrict__ xrow0 = (const float4*)(x + token0 * 64);
    const float4* __restrict__ xrow1 = (const float4*)(x + token1 * 64);

    float acc0[64], acc1[64];
    #pragma unroll
    for (int f = 0; f < 64; f++) { acc0[f] = 0.0f; acc1[f] = 0.0f; }

    #pragma unroll 2
    for (int kk = 0; kk < 16; kk++) {
        float4 xv0 = __ldg(xrow0 + kk);
        float4 xv1 = has1 ? __ldg(xrow1 + kk) : make_float4(0.f, 0.f, 0.f, 0.f);
        #pragma unroll
        for (int q = 0; q < 4; q++) {
            float xa = (q == 0) ? xv0.x : (q == 1) ? xv0.y : (q == 2) ? xv0.z : xv0.w;
            float xb = (q == 0) ? xv1.x : (q == 1) ? xv1.y : (q == 2) ? xv1.z : xv1.w;
            const float4* __restrict__ w4 = (const float4*)(Wt + (kk * 4 + q) * 64);
            #pragma unroll
            for (int e4 = 0; e4 < 16; e4++) {
                float4 w = w4[e4];   // broadcast LDS.128 -> feeds 8 FMAs
                acc0[e4 * 4 + 0] = fmaf(xa, w.x, acc0[e4 * 4 + 0]);
                acc0[e4 * 4 + 1] = fmaf(xa, w.y, acc0[e4 * 4 + 1]);
                acc0[e4 * 4 + 2] = fmaf(xa, w.z, acc0[e4 * 4 + 2]);
                acc0[e4 * 4 + 3] = fmaf(xa, w.w, acc0[e4 * 4 + 3]);
                acc1[e4 * 4 + 0] = fmaf(xb, w.x, acc1[e4 * 4 + 0]);
                acc1[e4 * 4 + 1] = fmaf(xb, w.y, acc1[e4 * 4 + 1]);
                acc1[e4 * 4 + 2] = fmaf(xb, w.z, acc1[e4 * 4 + 2]);
                acc1[e4 * 4 + 3] = fmaf(xb, w.w, acc1[e4 * 4 + 3]);
            }
        }
    }

    long long nt8 = (long long)n_tokens * 8;
    epilogue(acc0, tS + tid, out + token0 * 8, out + nt8 + token0 * 8);
    if (has1)
        epilogue(acc1, tS + tid + 64, out + token1 * 8, out + nt8 + token1 * 8);
}

extern "C" void kernel_launch(void* const* d_in, const int* in_sizes, int n_in,
                              void* d_out, int out_size)
{
    const float* x = (const float*)d_in[0];   // hidden_states [n_tokens, 64]
    const float* W = (const float*)d_in[1];   // weight        [64, 64]
    float* out = (float*)d_out;

    int n_tokens = in_sizes[0] / NEXPERT;
    int blocks = (n_tokens + TOKENS_PER_BLOCK - 1) / TOKENS_PER_BLOCK;

    moe_gate_kernel<<<blocks, NTHREADS>>>(x, W, out, n_tokens);
}